// round 8
// baseline (speedup 1.0000x reference)
#include <cuda_runtime.h>
#include <math.h>

// Problem constants (fixed-shape benchmark)
#define NN 50000
#define HH 16
#define RR 32
#define CC 8
#define EE 1600000

// Scratch (device globals; no allocation allowed)
__device__ float g_cnt[RR * NN];       // per-(rel,dst) edge counts, 6.4 MB
__device__ float g_x[NN * HH];         // layer-1 node features, 3.2 MB
__device__ float g_xw[RR * NN * CC];   // per-relation transformed feats, 51.2 MB
__device__ int   g_deg[NN];            // per-dst degree
__device__ int   g_off[NN];            // CSR offsets (exclusive scan of deg)
__device__ int   g_cur[NN];            // scatter cursors
__device__ int   g_eidx[EE];           // packed (src | rel<<16), bucketed by dst

// ---------------------------------------------------------------- (0) zero cnt/deg/cur
__global__ void k_zero() {
    int i = blockIdx.x * blockDim.x + threadIdx.x;
    int nc = RR * NN / 4;        // float4s of g_cnt
    int nd = NN / 4;             // int4s of g_deg / g_cur
    if (i < nc) ((float4*)g_cnt)[i] = make_float4(0.f, 0.f, 0.f, 0.f);
    else if (i < nc + nd) ((int4*)g_deg)[i - nc] = make_int4(0, 0, 0, 0);
    else if (i < nc + 2 * nd) ((int4*)g_cur)[i - nc - nd] = make_int4(0, 0, 0, 0);
}

// ---------------------------------------------------------------- (1) count: cnt[r,dst] and deg[dst]
__global__ void k_count(const int* __restrict__ ei, const int* __restrict__ et) {
    int e = blockIdx.x * blockDim.x + threadIdx.x;
    if (e >= EE) return;
    int dst = __ldg(ei + EE + e);
    int r   = __ldg(et + e);
    atomicAdd(&g_cnt[r * NN + dst], 1.0f);
    atomicAdd(&g_deg[dst], 1);
}

// ---------------------------------------------------------------- (2) exclusive scan deg -> off (1 block)
__global__ void k_scan() {
    __shared__ int ssum[1024];
    int t = threadIdx.x;
    const int CH = (NN + 1023) / 1024;   // 49
    int base = t * CH;
    int tot = 0;
    for (int i = 0; i < CH; i++) {
        int idx = base + i;
        if (idx < NN) tot += g_deg[idx];
    }
    ssum[t] = tot;
    __syncthreads();
    for (int d = 1; d < 1024; d <<= 1) {
        int v = 0;
        if (t >= d) v = ssum[t - d];
        __syncthreads();
        if (t >= d) ssum[t] += v;
        __syncthreads();
    }
    int run = (t > 0) ? ssum[t - 1] : 0;
    for (int i = 0; i < CH; i++) {
        int idx = base + i;
        if (idx < NN) { g_off[idx] = run; run += g_deg[idx]; }
    }
}

// ---------------------------------------------------------------- (3) scatter edges into CSR buckets
__global__ void k_scatter(const int* __restrict__ ei, const int* __restrict__ et) {
    int e = blockIdx.x * blockDim.x + threadIdx.x;
    if (e >= EE) return;
    int src = __ldg(ei + e);
    int dst = __ldg(ei + EE + e);
    int r   = __ldg(et + e);
    int pos = atomicAdd(&g_cur[dst], 1);
    g_eidx[g_off[dst] + pos] = src | (r << 16);
}

// ---------------------------------------------------------------- (4) layer 1, CSR node-major, fused act
// 16 lanes per node (lane = feature). No atomics.
__global__ void __launch_bounds__(256)
k_layer1(const float* __restrict__ w1, const float* __restrict__ root1,
         const float* __restrict__ b1) {
    int tid = blockIdx.x * 256 + threadIdx.x;
    int n = tid >> 4;
    int f = tid & 15;
    if (n >= NN) return;
    int start = __ldg(&g_off[n]);
    int m     = __ldg(&g_deg[n]);
    float acc = 0.f;
    int k = 0;
    for (; k + 4 <= m; k += 4) {
        int p0 = __ldg(&g_eidx[start + k]);
        int p1 = __ldg(&g_eidx[start + k + 1]);
        int p2 = __ldg(&g_eidx[start + k + 2]);
        int p3 = __ldg(&g_eidx[start + k + 3]);
        float c0 = __ldg(&g_cnt[(p0 >> 16) * NN + n]);
        float c1 = __ldg(&g_cnt[(p1 >> 16) * NN + n]);
        float c2 = __ldg(&g_cnt[(p2 >> 16) * NN + n]);
        float c3 = __ldg(&g_cnt[(p3 >> 16) * NN + n]);
        float w0 = __ldg(&w1[(((p0 >> 16) * NN + (p0 & 0xFFFF)) << 4) + f]);
        float w1v= __ldg(&w1[(((p1 >> 16) * NN + (p1 & 0xFFFF)) << 4) + f]);
        float w2v= __ldg(&w1[(((p2 >> 16) * NN + (p2 & 0xFFFF)) << 4) + f]);
        float w3v= __ldg(&w1[(((p3 >> 16) * NN + (p3 & 0xFFFF)) << 4) + f]);
        acc += w0 * __frcp_rn(c0);
        acc += w1v * __frcp_rn(c1);
        acc += w2v * __frcp_rn(c2);
        acc += w3v * __frcp_rn(c3);
    }
    for (; k < m; k++) {
        int p = __ldg(&g_eidx[start + k]);
        float c = __ldg(&g_cnt[(p >> 16) * NN + n]);
        float w = __ldg(&w1[(((p >> 16) * NN + (p & 0xFFFF)) << 4) + f]);
        acc += w * __frcp_rn(c);
    }
    float v = acc + __ldg(&root1[n * 16 + f]) + __ldg(&b1[f]);
    g_x[n * 16 + f] = fmaxf(v, 0.f);
}

// ---------------------------------------------------------------- (5) xw materialization
// xw[r, n, :] = x[n, :] @ w2[r]
__global__ void __launch_bounds__(256)
k_xw(const float* __restrict__ w2) {
    __shared__ float sw[2 * HH * CC];   // at most 2 relations per 256-thread block
    int idx0 = blockIdx.x * 256;
    int r0 = idx0 / NN;
    int r1 = (idx0 + 255) / NN;
    int nrel = r1 - r0 + 1;
    for (int i = threadIdx.x; i < nrel * HH * CC; i += 256)
        sw[i] = w2[r0 * HH * CC + i];
    __syncthreads();

    int idx = idx0 + threadIdx.x;       // over RR*NN
    if (idx >= RR * NN) return;
    int r = idx / NN;
    int n = idx - r * NN;
    const float4* xp = (const float4*)(g_x + n * HH);
    const float* w = sw + (r - r0) * HH * CC;

    float acc[CC];
    #pragma unroll
    for (int c = 0; c < CC; c++) acc[c] = 0.f;

    #pragma unroll
    for (int i4 = 0; i4 < 4; i4++) {
        float4 xv = xp[i4];
        float xs[4] = {xv.x, xv.y, xv.z, xv.w};
        #pragma unroll
        for (int j = 0; j < 4; j++) {
            int h = i4 * 4 + j;
            #pragma unroll
            for (int c = 0; c < CC; c++)
                acc[c] += xs[j] * w[h * CC + c];
        }
    }
    float4* op = (float4*)(g_xw + (size_t)idx * CC);
    op[0] = make_float4(acc[0], acc[1], acc[2], acc[3]);
    op[1] = make_float4(acc[4], acc[5], acc[6], acc[7]);
}

// ---------------------------------------------------------------- (6) layer 2 CSR + root2 + log_softmax
// 8 lanes per node (lane = class). No atomics, direct final store.
__global__ void __launch_bounds__(256)
k_layer2(const float* __restrict__ root2, const float* __restrict__ b2,
         float* __restrict__ out) {
    __shared__ float sr2[HH * CC];
    __shared__ float sb2[CC];
    if (threadIdx.x < HH * CC) sr2[threadIdx.x] = root2[threadIdx.x];
    if (threadIdx.x < CC) sb2[threadIdx.x] = b2[threadIdx.x];
    __syncthreads();

    int tid = blockIdx.x * 256 + threadIdx.x;
    int n = tid >> 3;
    int c = tid & 7;
    bool valid = (n < NN);
    if (!valid) n = NN - 1;             // keep whole warp active for shfl

    int start = __ldg(&g_off[n]);
    int m     = __ldg(&g_deg[n]);
    float acc = 0.f;
    int k = 0;
    for (; k + 4 <= m; k += 4) {
        int p0 = __ldg(&g_eidx[start + k]);
        int p1 = __ldg(&g_eidx[start + k + 1]);
        int p2 = __ldg(&g_eidx[start + k + 2]);
        int p3 = __ldg(&g_eidx[start + k + 3]);
        float c0 = __ldg(&g_cnt[(p0 >> 16) * NN + n]);
        float c1 = __ldg(&g_cnt[(p1 >> 16) * NN + n]);
        float c2 = __ldg(&g_cnt[(p2 >> 16) * NN + n]);
        float c3 = __ldg(&g_cnt[(p3 >> 16) * NN + n]);
        float v0 = __ldg(&g_xw[((size_t)(p0 >> 16) * NN + (p0 & 0xFFFF)) * CC + c]);
        float v1 = __ldg(&g_xw[((size_t)(p1 >> 16) * NN + (p1 & 0xFFFF)) * CC + c]);
        float v2 = __ldg(&g_xw[((size_t)(p2 >> 16) * NN + (p2 & 0xFFFF)) * CC + c]);
        float v3 = __ldg(&g_xw[((size_t)(p3 >> 16) * NN + (p3 & 0xFFFF)) * CC + c]);
        acc += v0 * __frcp_rn(c0);
        acc += v1 * __frcp_rn(c1);
        acc += v2 * __frcp_rn(c2);
        acc += v3 * __frcp_rn(c3);
    }
    for (; k < m; k++) {
        int p = __ldg(&g_eidx[start + k]);
        float cf = __ldg(&g_cnt[(p >> 16) * NN + n]);
        float v = __ldg(&g_xw[((size_t)(p >> 16) * NN + (p & 0xFFFF)) * CC + c]);
        acc += v * __frcp_rn(cf);
    }

    // + x[n] @ root2 + b2
    const float4* xp = (const float4*)(g_x + n * HH);
    float o = acc + sb2[c];
    #pragma unroll
    for (int i4 = 0; i4 < 4; i4++) {
        float4 xv = __ldg(&xp[i4]);
        o += xv.x * sr2[(i4 * 4 + 0) * CC + c];
        o += xv.y * sr2[(i4 * 4 + 1) * CC + c];
        o += xv.z * sr2[(i4 * 4 + 2) * CC + c];
        o += xv.w * sr2[(i4 * 4 + 3) * CC + c];
    }

    // log_softmax across the 8-lane class group
    float mx = o;
    #pragma unroll
    for (int d = 1; d < 8; d <<= 1)
        mx = fmaxf(mx, __shfl_xor_sync(0xFFFFFFFF, mx, d));
    float s = expf(o - mx);
    #pragma unroll
    for (int d = 1; d < 8; d <<= 1)
        s += __shfl_xor_sync(0xFFFFFFFF, s, d);
    if (valid) out[n * CC + c] = o - mx - logf(s);
}

// ---------------------------------------------------------------- launch
extern "C" void kernel_launch(void* const* d_in, const int* in_sizes, int n_in,
                              void* d_out, int out_size) {
    const int*   ei    = (const int*)  d_in[0];  // [2, E]
    const int*   et    = (const int*)  d_in[1];  // [E]
    const float* w1    = (const float*)d_in[2];  // [R, N, H]
    const float* root1 = (const float*)d_in[3];  // [N, H]
    const float* b1    = (const float*)d_in[4];  // [H]
    const float* w2    = (const float*)d_in[5];  // [R, H, C]
    const float* root2 = (const float*)d_in[6];  // [H, C]
    const float* b2    = (const float*)d_in[7];  // [C]
    float* out = (float*)d_out;                  // [N, C]

    int zt = RR * NN / 4 + 2 * (NN / 4);
    k_zero   <<<(zt + 255) / 256, 256>>>();
    k_count  <<<(EE + 255) / 256, 256>>>(ei, et);
    k_scan   <<<1, 1024>>>();
    k_scatter<<<(EE + 255) / 256, 256>>>(ei, et);
    k_layer1 <<<(NN * 16 + 255) / 256, 256>>>(w1, root1, b1);
    k_xw     <<<(RR * NN + 255) / 256, 256>>>(w2);
    k_layer2 <<<(NN * 8 + 255) / 256, 256>>>(root2, b2, out);
}